// round 5
// baseline (speedup 1.0000x reference)
#include <cuda_runtime.h>
#include <cuda_fp16.h>
#include <cstdint>

// ---------------------------------------------------------------------------
// out[512, 65536] = inputs[512,256] @ features[65536,256]^T   (fp32 in/out)
//
// Toolchain: compute_103 virtual arch -> no tcgen05; tensor path is
// ldmatrix + mma.sync.m16n8k16 (HMMA).
//
//  1) convert_kernel: fp32 -> fp16 streaming pass into __device__ globals.
//  2) gemm_kernel: 148 CTAs x 256 threads, CTA tile M=128 x N=256 x K=256.
//     8 warps as 2(m) x 4(n), warp tile 64x64 (0.25 ldmatrix.x4 per MMA --
//     crossbar relief vs 0.375/0.5 in R3/R4). A (64KB) smem-resident;
//     B streamed as K=64 chunks (32KB) through a 4-stage cp.async ring,
//     prefetch distance 3, one __syncthreads per chunk (multistage pattern).
// ---------------------------------------------------------------------------

#define GY 37                            // grid (4, 37) = 148 CTAs
#define BLOCK 256
#define NBLK 256                         // 65536 / 256 n-blocks
#define SMEM_BYTES (65536 + 4 * 32768)   // A 64KB + 4 B stages = 192KB

__device__ __align__(256) __half g_fB[65536 * 256];  // features fp16
__device__ __align__(256) __half g_fA[512 * 256];    // inputs fp16

// ---------------- convert: fp32 -> fp16 streaming ----------------
__global__ void __launch_bounds__(256) convert_kernel(
    const float* __restrict__ features, const float* __restrict__ inputs)
{
    const int stride = gridDim.x * blockDim.x;
    const float4* f4 = reinterpret_cast<const float4*>(features);
    uint2* b4 = reinterpret_cast<uint2*>(g_fB);
    for (int i = blockIdx.x * blockDim.x + threadIdx.x; i < 4194304; i += stride) {
        float4 v = f4[i];
        __half2 h0 = __floats2half2_rn(v.x, v.y);
        __half2 h1 = __floats2half2_rn(v.z, v.w);
        b4[i] = make_uint2(*reinterpret_cast<uint32_t*>(&h0),
                           *reinterpret_cast<uint32_t*>(&h1));
    }
    const float4* i4 = reinterpret_cast<const float4*>(inputs);
    uint2* a4 = reinterpret_cast<uint2*>(g_fA);
    for (int i = blockIdx.x * blockDim.x + threadIdx.x; i < 32768; i += stride) {
        float4 v = i4[i];
        __half2 h0 = __floats2half2_rn(v.x, v.y);
        __half2 h1 = __floats2half2_rn(v.z, v.w);
        a4[i] = make_uint2(*reinterpret_cast<uint32_t*>(&h0),
                           *reinterpret_cast<uint32_t*>(&h1));
    }
}

// ---------------- gemm helpers ----------------
__device__ __forceinline__ uint32_t smem_u32(const void* p) {
    uint32_t a;
    asm("{ .reg .u64 t; cvta.to.shared.u64 t, %1; cvt.u32.u64 %0, t; }"
        : "=r"(a) : "l"(p));
    return a;
}

// A rows are 512B (256 halves): XOR (row&7) into 16B-chunk bits [4:7).
__device__ __forceinline__ uint32_t swzA(uint32_t off) {
    return off ^ (((off >> 9) & 7u) << 4);
}
// B chunk rows are 128B (64 halves): XOR (row&7) into bits [4:7).
__device__ __forceinline__ uint32_t swzB(uint32_t off) {
    return off ^ (((off >> 7) & 7u) << 4);
}

__device__ __forceinline__ void cp16(uint32_t dst, const void* src) {
    asm volatile("cp.async.cg.shared.global [%0], [%1], 16;"
                 :: "r"(dst), "l"(src));
}

__device__ __forceinline__ void ldm_x4(uint32_t* r, uint32_t addr) {
    asm volatile(
        "ldmatrix.sync.aligned.m8n8.x4.shared.b16 {%0,%1,%2,%3}, [%4];"
        : "=r"(r[0]), "=r"(r[1]), "=r"(r[2]), "=r"(r[3]) : "r"(addr));
}

__device__ __forceinline__ void mma_16816(float* c, const uint32_t* a,
                                          uint32_t b0, uint32_t b1) {
    asm volatile(
        "mma.sync.aligned.m16n8k16.row.col.f32.f16.f16.f32 "
        "{%0,%1,%2,%3}, {%4,%5,%6,%7}, {%8,%9}, {%0,%1,%2,%3};"
        : "+f"(c[0]), "+f"(c[1]), "+f"(c[2]), "+f"(c[3])
        : "r"(a[0]), "r"(a[1]), "r"(a[2]), "r"(a[3]), "r"(b0), "r"(b1));
}

// A tile: 128 rows x 256 halves (64KB), swizzled.
__device__ __forceinline__ void issue_A(uint32_t sA, const __half* g, int tid) {
#pragma unroll
    for (int q = tid; q < 4096; q += BLOCK) {
        int row = q >> 5;               // 32 x 16B per 512B row
        int c   = q & 31;
        cp16(sA + swzA((uint32_t)(row * 512 + c * 16)), g + row * 256 + c * 8);
    }
}

// B chunk: 256 n-rows x 64 halves (32KB), swizzled.
__device__ __forceinline__ void issue_B(uint32_t sB, const __half* gbase,
                                        int kc, int tid) {
#pragma unroll
    for (int q = tid; q < 2048; q += BLOCK) {
        int n = q >> 3;                 // 8 x 16B per 128B row
        int c = q & 7;
        cp16(sB + swzB((uint32_t)(n * 128 + c * 16)),
             gbase + (size_t)n * 256 + kc * 64 + c * 8);
    }
}

__global__ void __launch_bounds__(BLOCK, 1) gemm_kernel(float* __restrict__ out)
{
    extern __shared__ char smem[];
    const uint32_t sA = smem_u32(smem);             // 64KB
    const uint32_t sB = sA + 65536u;                // 4 x 32KB ring

    const int tid = threadIdx.x;
    const int wid = tid >> 5;
    const int lid = tid & 31;
    const int wm = wid >> 2;     // 0..1 (64 m-rows)
    const int wn = wid & 3;      // 0..3 (64 n-rows)
    const int m_super = blockIdx.x;   // 0..3
    const int j0 = blockIdx.y;        // n-block, stride GY

    const int nj = (NBLK - 1 - j0) / GY + 1;   // j-iterations for this CTA
    const int nchunks = nj * 4;

    // Prologue: A + chunk 0 in one group, chunks 1, 2 in their own groups.
    issue_A(sA, g_fA + m_super * 128 * 256, tid);
    issue_B(sB, g_fB + (size_t)j0 * 256 * 256, 0, tid);
    asm volatile("cp.async.commit_group;");
    issue_B(sB + 32768u, g_fB + (size_t)j0 * 256 * 256, 1, tid);
    asm volatile("cp.async.commit_group;");
    issue_B(sB + 65536u, g_fB + (size_t)j0 * 256 * 256, 2, tid);
    asm volatile("cp.async.commit_group;");

    // per-lane ldmatrix address components
    const int a_row = lid & 15;
    const int a_kb  = (lid >> 4) * 16;
    const int b_row = (lid & 7) + ((lid >> 4) * 8);
    const int b_kb  = ((lid >> 3) & 1) * 16;

    int t = 0;   // global chunk counter
    for (int ji = 0; ji < nj; ++ji) {
        const int jv = j0 + ji * GY;

        float acc[4][8][4];
#pragma unroll
        for (int mf = 0; mf < 4; ++mf)
#pragma unroll
            for (int nf = 0; nf < 8; ++nf)
#pragma unroll
                for (int e = 0; e < 4; ++e) acc[mf][nf][e] = 0.0f;

#pragma unroll
        for (int kc = 0; kc < 4; ++kc, ++t) {
            asm volatile("cp.async.wait_group 2;");
            __syncthreads();

            // Prefetch chunk t+3 into the ring slot freed at t-1.
            {
                const int tp = t + 3;
                if (tp < nchunks) {
                    const int jp = j0 + (tp >> 2) * GY;
                    issue_B(sB + (uint32_t)(tp & 3) * 32768u,
                            g_fB + (size_t)jp * 256 * 256, tp & 3, tid);
                }
                asm volatile("cp.async.commit_group;");
            }

            const uint32_t sBc = sB + (uint32_t)(t & 3) * 32768u;

#pragma unroll
            for (int ks = 0; ks < 4; ++ks) {
                const uint32_t kbA = (uint32_t)(kc * 4 + ks) * 32;
                const uint32_t kbB = (uint32_t)ks * 32;
                uint32_t a[4][4];
#pragma unroll
                for (int mf = 0; mf < 4; ++mf) {
                    int row = wm * 64 + mf * 16 + a_row;
                    ldm_x4(a[mf], sA + swzA((uint32_t)(row * 512) + kbA + a_kb));
                }
                uint32_t b[4][4];
#pragma unroll
                for (int ng = 0; ng < 4; ++ng) {
                    int nrow = wn * 64 + ng * 16 + b_row;
                    ldm_x4(b[ng], sBc + swzB((uint32_t)(nrow * 128) + kbB + b_kb));
                }
#pragma unroll
                for (int mf = 0; mf < 4; ++mf)
#pragma unroll
                    for (int nf = 0; nf < 8; ++nf)
                        mma_16816(acc[mf][nf], a[mf],
                                  b[nf >> 1][(nf & 1) * 2 + 0],
                                  b[nf >> 1][(nf & 1) * 2 + 1]);
            }
        }

        // Epilogue: direct GMEM float2 stores (overlaps in-flight prefetches)
        const int row0 = m_super * 128 + wm * 64 + (lid >> 2);
        const int col0 = jv * 256 + wn * 64 + (lid & 3) * 2;
#pragma unroll
        for (int mf = 0; mf < 4; ++mf) {
#pragma unroll
            for (int nf = 0; nf < 8; ++nf) {
                const int r = row0 + mf * 16;
                const int c = col0 + nf * 8;
                float2 v0 = make_float2(acc[mf][nf][0], acc[mf][nf][1]);
                float2 v1 = make_float2(acc[mf][nf][2], acc[mf][nf][3]);
                *reinterpret_cast<float2*>(out + (size_t)r * 65536 + c) = v0;
                *reinterpret_cast<float2*>(out + (size_t)(r + 8) * 65536 + c) = v1;
            }
        }
    }
}

extern "C" void kernel_launch(void* const* d_in, const int* in_sizes, int n_in,
                              void* d_out, int out_size) {
    // metadata order: inputs f32[512,256], indexes i64[512],
    //                 features f32[65536,256], mIoU f32[65536], IoU f32[512];
    //                 output f32[512,65536]
    const float* inputs   = (const float*)d_in[0];
    const float* features = (const float*)d_in[2];
    float* out = (float*)d_out;

    convert_kernel<<<1184, 256>>>(features, inputs);

    cudaFuncSetAttribute(gemm_kernel,
                         cudaFuncAttributeMaxDynamicSharedMemorySize, SMEM_BYTES);
    // grid.x = m_super (fast): the 4 CTAs sharing each B tile run concurrently
    gemm_kernel<<<dim3(4, GY), BLOCK, SMEM_BYTES>>>(out);
}

// round 6
// speedup vs baseline: 1.1112x; 1.1112x over previous
#include <cuda_runtime.h>
#include <cuda_fp16.h>
#include <cstdint>

// ---------------------------------------------------------------------------
// out[512, 65536] = inputs[512,256] @ features[65536,256]^T   (fp32 in/out)
//
// Toolchain: compute_103 virtual arch -> no tcgen05; tensor path is
// ldmatrix + mma.sync.m16n8k16 (HMMA, rt ~4 cyc/SMSP measured).
//
//  1) convert_kernel: fp32 -> fp16 streaming pass into __device__ globals.
//  2) gemm_kernel: persistent 148 CTAs x 256 threads, CTA tile
//     M=128 x N=128 x K=256 (A smem-resident, B double-buffered 64KB tiles
//     via cp.async, prefetch distance 2). Warp tile 64x32 (best measured).
//     NEW vs R3: k-step software pipelining -- LDSMs for k-step ks+1 are
//     issued before the 32-MMA block of ks (double-buffered fragment regs),
//     hiding the ~30-50cyc ldmatrix latency that capped tensor util at 48%.
//     Epilogue uses st.global.cs (streaming) to keep B hot in L2.
// ---------------------------------------------------------------------------

#define GY 37                       // grid.y; 4*37 = 148 CTAs (1/SM)
#define BLOCK 256
#define SMEM_BYTES (3 * 65536)      // A 64KB + B double buffer 2x64KB

__device__ __align__(256) __half g_fB[65536 * 256];  // features fp16
__device__ __align__(256) __half g_fA[512 * 256];    // inputs fp16

// ---------------- convert: fp32 -> fp16 streaming ----------------
__global__ void __launch_bounds__(256) convert_kernel(
    const float* __restrict__ features, const float* __restrict__ inputs)
{
    const int stride = gridDim.x * blockDim.x;
    const float4* f4 = reinterpret_cast<const float4*>(features);
    uint2* b4 = reinterpret_cast<uint2*>(g_fB);
    for (int i = blockIdx.x * blockDim.x + threadIdx.x; i < 4194304; i += stride) {
        float4 v = f4[i];
        __half2 h0 = __floats2half2_rn(v.x, v.y);
        __half2 h1 = __floats2half2_rn(v.z, v.w);
        b4[i] = make_uint2(*reinterpret_cast<uint32_t*>(&h0),
                           *reinterpret_cast<uint32_t*>(&h1));
    }
    const float4* i4 = reinterpret_cast<const float4*>(inputs);
    uint2* a4 = reinterpret_cast<uint2*>(g_fA);
    for (int i = blockIdx.x * blockDim.x + threadIdx.x; i < 32768; i += stride) {
        float4 v = i4[i];
        __half2 h0 = __floats2half2_rn(v.x, v.y);
        __half2 h1 = __floats2half2_rn(v.z, v.w);
        a4[i] = make_uint2(*reinterpret_cast<uint32_t*>(&h0),
                           *reinterpret_cast<uint32_t*>(&h1));
    }
}

// ---------------- gemm helpers ----------------
__device__ __forceinline__ uint32_t smem_u32(const void* p) {
    uint32_t a;
    asm("{ .reg .u64 t; cvta.to.shared.u64 t, %1; cvt.u32.u64 %0, t; }"
        : "=r"(a) : "l"(p));
    return a;
}

// Row = 512B (256 halves). Swizzle: XOR 16B-chunk index with (row & 7).
__device__ __forceinline__ uint32_t swz(uint32_t off) {
    return off ^ (((off >> 9) & 7u) << 4);
}

__device__ __forceinline__ void cp16(uint32_t dst, const void* src) {
    asm volatile("cp.async.cg.shared.global [%0], [%1], 16;"
                 :: "r"(dst), "l"(src));
}

__device__ __forceinline__ void ldm_x4(uint32_t* r, uint32_t addr) {
    asm volatile(
        "ldmatrix.sync.aligned.m8n8.x4.shared.b16 {%0,%1,%2,%3}, [%4];"
        : "=r"(r[0]), "=r"(r[1]), "=r"(r[2]), "=r"(r[3]) : "r"(addr));
}

__device__ __forceinline__ void mma_16816(float* c, const uint32_t* a,
                                          uint32_t b0, uint32_t b1) {
    asm volatile(
        "mma.sync.aligned.m16n8k16.row.col.f32.f16.f16.f32 "
        "{%0,%1,%2,%3}, {%4,%5,%6,%7}, {%8,%9}, {%0,%1,%2,%3};"
        : "+f"(c[0]), "+f"(c[1]), "+f"(c[2]), "+f"(c[3])
        : "r"(a[0]), "r"(a[1]), "r"(a[2]), "r"(a[3]), "r"(b0), "r"(b1));
}

__device__ __forceinline__ void stg_cs_v2(float* p, float x, float y) {
    asm volatile("st.global.cs.v2.f32 [%0], {%1, %2};"
                 :: "l"(p), "f"(x), "f"(y) : "memory");
}

// Issue cp.async for a full 128x256-half tile (64KB) into swizzled smem.
__device__ __forceinline__ void issue_tile_copy(uint32_t sdst,
                                                const __half* gsrc, int tid) {
#pragma unroll
    for (int q = tid; q < 4096; q += BLOCK) {
        int row = q >> 5;        // 32 x 16B chunks per 512B row
        int c   = q & 31;
        cp16(sdst + swz((uint32_t)(row * 512 + c * 16)),
             gsrc + row * 256 + c * 8);
    }
}

__global__ void __launch_bounds__(BLOCK, 1) gemm_kernel(float* __restrict__ out)
{
    extern __shared__ char smem[];
    const uint32_t sA  = smem_u32(smem);       // 128 x 512B
    const uint32_t sB0 = sA + 65536u;
    const uint32_t sB1 = sA + 131072u;

    const int tid = threadIdx.x;
    const int wid = tid >> 5;
    const int lid = tid & 31;
    const int wm = wid >> 2;    // 0..1  (64 m-rows each)
    const int wn = wid & 3;     // 0..3  (32 n-rows each)
    const int m_super = blockIdx.x;   // 0..3  (rows m_super*128 .. +128)
    const int j0 = blockIdx.y;        // first n-block; stride GY

    // Prologue: A tile + first two B tiles in flight (3 commit groups).
    issue_tile_copy(sA, g_fA + m_super * 128 * 256, tid);
    asm volatile("cp.async.commit_group;");
    issue_tile_copy(sB0, g_fB + (size_t)j0 * 128 * 256, tid);
    asm volatile("cp.async.commit_group;");
    issue_tile_copy(sB1, g_fB + (size_t)(j0 + GY) * 128 * 256, tid);
    asm volatile("cp.async.commit_group;");

    // Per-lane ldmatrix address components
    const int a_row = lid & 15;
    const int a_kb  = (lid >> 4) * 16;                 // bytes
    const int b_row = (lid & 7) + ((lid >> 4) * 8);
    const int b_kb  = ((lid >> 3) & 1) * 16;           // bytes

    int parity = 0;
    for (int j = j0; j < 512; j += GY) {
        asm volatile("cp.async.wait_group 1;");
        __syncthreads();
        const uint32_t sB = parity ? sB1 : sB0;

        float acc[4][4][4];
#pragma unroll
        for (int mf = 0; mf < 4; ++mf)
#pragma unroll
            for (int nf = 0; nf < 4; ++nf)
#pragma unroll
                for (int e = 0; e < 4; ++e) acc[mf][nf][e] = 0.0f;

        // Double-buffered fragments: LDSMs for ks+1 issue before ks's MMAs.
        uint32_t a[2][4][4];
        uint32_t b[2][2][4];

        // Preload k-step 0 into buffer 0.
#pragma unroll
        for (int mf = 0; mf < 4; ++mf) {
            int row = wm * 64 + mf * 16 + a_row;
            ldm_x4(a[0][mf], sA + swz((uint32_t)(row * 512) + 0 + a_kb));
        }
#pragma unroll
        for (int ng = 0; ng < 2; ++ng) {
            int nrow = wn * 32 + ng * 16 + b_row;
            ldm_x4(b[0][ng], sB + swz((uint32_t)(nrow * 512) + 0 + b_kb));
        }

#pragma unroll
        for (int ks = 0; ks < 16; ++ks) {
            const int cur = ks & 1;
            if (ks < 15) {
                const int nxt = cur ^ 1;
                const uint32_t kb = (uint32_t)(ks + 1) * 32;
#pragma unroll
                for (int mf = 0; mf < 4; ++mf) {
                    int row = wm * 64 + mf * 16 + a_row;
                    ldm_x4(a[nxt][mf],
                           sA + swz((uint32_t)(row * 512) + kb + a_kb));
                }
#pragma unroll
                for (int ng = 0; ng < 2; ++ng) {
                    int nrow = wn * 32 + ng * 16 + b_row;
                    ldm_x4(b[nxt][ng],
                           sB + swz((uint32_t)(nrow * 512) + kb + b_kb));
                }
            }
#pragma unroll
            for (int mf = 0; mf < 4; ++mf)
#pragma unroll
                for (int nf = 0; nf < 4; ++nf)
                    mma_16816(acc[mf][nf], a[cur][mf],
                              b[cur][nf >> 1][(nf & 1) * 2 + 0],
                              b[cur][nf >> 1][(nf & 1) * 2 + 1]);
        }

        __syncthreads();   // all warps done reading sB(parity)

        // Prefetch B tile j + 2*GY into the freed buffer; overlaps epilogue
        // stores and the next iteration's MMA.
        int pf = j + 2 * GY;
        if (pf < 512)
            issue_tile_copy(parity ? sB1 : sB0,
                            g_fB + (size_t)pf * 128 * 256, tid);
        asm volatile("cp.async.commit_group;");

        // Epilogue: streaming GMEM float2 stores
        const int row0 = m_super * 128 + wm * 64 + (lid >> 2);
        const int col0 = j * 128 + wn * 32 + (lid & 3) * 2;
#pragma unroll
        for (int mf = 0; mf < 4; ++mf) {
#pragma unroll
            for (int nf = 0; nf < 4; ++nf) {
                const int r = row0 + mf * 16;
                const int c = col0 + nf * 8;
                stg_cs_v2(out + (size_t)r * 65536 + c,
                          acc[mf][nf][0], acc[mf][nf][1]);
                stg_cs_v2(out + (size_t)(r + 8) * 65536 + c,
                          acc[mf][nf][2], acc[mf][nf][3]);
            }
        }
        parity ^= 1;
    }
}

extern "C" void kernel_launch(void* const* d_in, const int* in_sizes, int n_in,
                              void* d_out, int out_size) {
    // metadata order: inputs f32[512,256], indexes i64[512],
    //                 features f32[65536,256], mIoU f32[65536], IoU f32[512];
    //                 output f32[512,65536]
    const float* inputs   = (const float*)d_in[0];
    const float* features = (const float*)d_in[2];
    float* out = (float*)d_out;

    convert_kernel<<<1184, 256>>>(features, inputs);

    cudaFuncSetAttribute(gemm_kernel,
                         cudaFuncAttributeMaxDynamicSharedMemorySize, SMEM_BYTES);
    // grid.x = m_super (fast): the 4 CTAs sharing each B tile run concurrently
    gemm_kernel<<<dim3(4, GY), BLOCK, SMEM_BYTES>>>(out);
}